// round 4
// baseline (speedup 1.0000x reference)
#include <cuda_runtime.h>
#include <cstdint>

#define TOKENS   16384
#define DIM      4096
#define NEXP     64
#define TOPK     8
#define BT       64            // tokens per block
#define KC       32            // k-chunk
#define NC       (DIM / KC)    // 128 chunks
#define NTHREADS 128

#define SROWX    68            // xs row: 64 tokens + pad (16B aligned, bank shift 4)
#define SROWW    132           // ws row: 128 dup-w + pad (16B aligned, bank shift 4)
#define STAGE_FLOATS (KC*SROWX + KC*SROWW)   // 2176 + 4224 = 6400
#define STAGE_BYTES  (STAGE_FLOATS * 4)      // 25600
#define SMEM_BYTES   (2 * STAGE_BYTES)       // 51200

#define SROWL    66            // logits row in epilogue
#define NEG_INF (-3.0e38f)

// W pre-transposed + duplicated: g_wdup[k][2e] = g_wdup[k][2e+1] = W[e][k]
__device__ float g_wdup[DIM * 2 * NEXP];

__global__ void wdup_kernel(const float* __restrict__ W)
{
    int idx = blockIdx.x * blockDim.x + threadIdx.x;   // over 64*4096
    int e = idx >> 12;          // expert
    int k = idx & 4095;         // dim
    float v = W[idx];           // coalesced read
    g_wdup[k * 128 + 2 * e]     = v;
    g_wdup[k * 128 + 2 * e + 1] = v;
}

__device__ __forceinline__ unsigned smem_u32(const void* p) {
    return (unsigned)__cvta_generic_to_shared(p);
}

__global__ __launch_bounds__(NTHREADS, 4)
void router_kernel(const float* __restrict__ x,
                   float* __restrict__ out,
                   int out_size)
{
    extern __shared__ float sm[];
    const unsigned sbase = smem_u32(sm);

    const int tid  = threadIdx.x;
    const int tok0 = blockIdx.x * BT;

    const int eg = tid & 15;    // experts e0 = eg*4 .. +3 (dup cols 8eg..8eg+7)
    const int tg = tid >> 4;    // tokens  t0 = tg*8 .. +7 (4 packed pairs)
    const int t0 = tg * 8;

    // x loader mapping: 2 threads per token row, 64B each (4 float4)
    const int lrow  = tid >> 1;      // token row 0..63
    const int lhalf = tid & 1;       // k-half within chunk
    const float* xsrc = x + (size_t)(tok0 + lrow) * DIM + lhalf * 16;

    // acc[pair p][expert j], packed f32x2 over (t0+2p, t0+2p+1)
    unsigned long long acc[4][4];
#pragma unroll
    for (int p = 0; p < 4; p++)
#pragma unroll
        for (int j = 0; j < 4; j++) acc[p][j] = 0ull;

    float4 xv[4];

    // ---- prologue: x chunk 0 -> regs, W chunk 0 -> smem stage 0 via cp.async ----
#pragma unroll
    for (int f = 0; f < 4; f++)
        xv[f] = *(const float4*)(xsrc + f * 4);

    {
        const float* wsrc = g_wdup;   // chunk 0
#pragma unroll
        for (int i = 0; i < 8; i++) {
            int m   = i * NTHREADS + tid;          // 16B unit index, 0..1023
            int kkw = m >> 5, col = m & 31;
            unsigned dst = sbase + (unsigned)((KC * SROWX + kkw * SROWW + col * 4) * 4);
            asm volatile("cp.async.cg.shared.global [%0], [%1], 16;\n"
                         :: "r"(dst), "l"(wsrc + m * 4));
        }
        asm volatile("cp.async.commit_group;\n");
    }

    for (int c = 0; c < NC; c++) {
        const unsigned stg = (unsigned)(c & 1) * STAGE_BYTES;
        const unsigned xs_b = sbase + stg;
        const unsigned ws_b = xs_b + KC * SROWX * 4;

        __syncthreads();   // buffer (c&1): readers from iteration c-2 are done

        // store prefetched x chunk c (transposed [kk][token])
#pragma unroll
        for (int f = 0; f < 4; f++) {
            int kk = lhalf * 16 + f * 4;
            float* xd = sm + (c & 1) * STAGE_FLOATS + kk * SROWX + lrow;
            xd[0 * SROWX] = xv[f].x;
            xd[1 * SROWX] = xv[f].y;
            xd[2 * SROWX] = xv[f].z;
            xd[3 * SROWX] = xv[f].w;
        }

        if (c + 1 < NC) {
            // prefetch x chunk c+1 -> regs
            const float* xs2 = xsrc + (c + 1) * KC;
#pragma unroll
            for (int f = 0; f < 4; f++)
                xv[f] = *(const float4*)(xs2 + f * 4);

            // cp.async W chunk c+1 -> other stage
            const float* wsrc = g_wdup + (size_t)(c + 1) * (KC * 128);
            const unsigned wdst_b = sbase + (unsigned)((c + 1) & 1) * STAGE_BYTES
                                    + KC * SROWX * 4;
#pragma unroll
            for (int i = 0; i < 8; i++) {
                int m   = i * NTHREADS + tid;
                int kkw = m >> 5, col = m & 31;
                unsigned dst = wdst_b + (unsigned)((kkw * SROWW + col * 4) * 4);
                asm volatile("cp.async.cg.shared.global [%0], [%1], 16;\n"
                             :: "r"(dst), "l"(wsrc + m * 4));
            }
            asm volatile("cp.async.commit_group;\n");
            asm volatile("cp.async.wait_group 1;\n");
        } else {
            asm volatile("cp.async.wait_group 0;\n");
        }

        __syncthreads();

        // ---- compute chunk c: per kk -> 4 LDS.v2.u64 + 16 FFMA2, zero MOVs ----
#pragma unroll 8
        for (int kk = 0; kk < KC; kk++) {
            unsigned xaddr = xs_b + (unsigned)((kk * SROWX + t0) * 4);
            unsigned waddr = ws_b + (unsigned)((kk * SROWW + eg * 8) * 4);

            unsigned long long xp0, xp1, xp2, xp3;
            asm("ld.shared.v2.u64 {%0,%1}, [%2];"
                : "=l"(xp0), "=l"(xp1) : "r"(xaddr));
            asm("ld.shared.v2.u64 {%0,%1}, [%2];"
                : "=l"(xp2), "=l"(xp3) : "r"(xaddr + 16));

            unsigned long long wd0, wd1, wd2, wd3;
            asm("ld.shared.v2.u64 {%0,%1}, [%2];"
                : "=l"(wd0), "=l"(wd1) : "r"(waddr));
            asm("ld.shared.v2.u64 {%0,%1}, [%2];"
                : "=l"(wd2), "=l"(wd3) : "r"(waddr + 16));

#define FF(P, XP) \
            asm("fma.rn.f32x2 %0, %1, %2, %0;" : "+l"(acc[P][0]) : "l"(XP), "l"(wd0)); \
            asm("fma.rn.f32x2 %0, %1, %2, %0;" : "+l"(acc[P][1]) : "l"(XP), "l"(wd1)); \
            asm("fma.rn.f32x2 %0, %1, %2, %0;" : "+l"(acc[P][2]) : "l"(XP), "l"(wd2)); \
            asm("fma.rn.f32x2 %0, %1, %2, %0;" : "+l"(acc[P][3]) : "l"(XP), "l"(wd3));
            FF(0, xp0) FF(1, xp1) FF(2, xp2) FF(3, xp3)
#undef FF
        }
    }

    // ---- dump logits to smem (stage-0 region, last compute used stage 1) ----
    float* lg = sm;   // lg[64][SROWL], 16.9KB
    __syncthreads();
#pragma unroll
    for (int p = 0; p < 4; p++) {
#pragma unroll
        for (int j = 0; j < 4; j++) {
            float lo, hi;
            asm("mov.b64 {%0, %1}, %2;" : "=f"(lo), "=f"(hi) : "l"(acc[p][j]));
            int e = eg * 4 + j;
            lg[(t0 + 2 * p)     * SROWL + e] = lo;
            lg[(t0 + 2 * p + 1) * SROWL + e] = hi;
        }
    }
    __syncthreads();

    // ---- fused top-8 + softmax: one thread per token ----
    if (tid < BT) {
        const int t = tid;
        float* row = lg + t * SROWL;

        float cv[TOPK];
        int   ci[TOPK];
#pragma unroll
        for (int r = 0; r < TOPK; r++) {
            float best = NEG_INF;
            int   bi   = 0;
            for (int e = 0; e < NEXP; e++) {
                float v = row[e];
                if (v > best) { best = v; bi = e; }  // strict >: ties -> lowest index
            }
            row[bi] = NEG_INF;
            cv[r] = best;
            ci[r] = bi;
        }

        float m = cv[0];
        float ex[TOPK], s = 0.f;
#pragma unroll
        for (int r = 0; r < TOPK; r++) { ex[r] = __expf(cv[r] - m); s += ex[r]; }
        float inv = 1.f / s;

        int gt = tok0 + t;
#pragma unroll
        for (int r = 0; r < TOPK; r++)
            out[gt * TOPK + r] = ex[r] * inv;

        if (out_size >= 2 * TOKENS * TOPK) {
#pragma unroll
            for (int r = 0; r < TOPK; r++)
                out[TOKENS * TOPK + gt * TOPK + r] = (float)ci[r];
        }
    }
}

extern "C" void kernel_launch(void* const* d_in, const int* in_sizes, int n_in,
                              void* d_out, int out_size)
{
    const float* x = (const float*)d_in[0];   // [16384, 4096]
    const float* W = (const float*)d_in[1];   // [64, 4096]
    float* out = (float*)d_out;

    static bool attr_set = false;
    cudaFuncSetAttribute(router_kernel,
                         cudaFuncAttributeMaxDynamicSharedMemorySize, SMEM_BYTES);
    (void)attr_set;

    wdup_kernel<<<(NEXP * DIM) / 256, 256>>>(W);
    router_kernel<<<TOKENS / BT, NTHREADS, SMEM_BYTES>>>(x, out, out_size);
}

// round 6
// speedup vs baseline: 1.1831x; 1.1831x over previous
#include <cuda_runtime.h>
#include <cstdint>

#define TOKENS   16384
#define DIM      4096
#define NEXP     64
#define TOPK     8
#define BT       128           // tokens per block
#define KC       32            // k-chunk
#define NC       (DIM / KC)    // 128 chunks
#define NTHREADS 128

#define SXROW    33                          // x row stride in floats (odd -> conflict-free col reads)
#define XS_FLOATS (BT * SXROW)               // 4224
#define WS_FLOATS (KC * NEXP)                // 2048
#define STAGE_FLOATS (XS_FLOATS + WS_FLOATS) // 6272
#define STAGE_BYTES  (STAGE_FLOATS * 4)      // 25088
#define SMEM_BYTES   (2 * STAGE_BYTES)       // 50176

#define SROWL    66
#define NEG_INF (-3.0e38f)

// W transposed: g_wt[k*64 + e] = W[e][k]
__device__ float g_wt[DIM * NEXP];

__global__ void wt_kernel(const float* __restrict__ W)
{
    int idx = blockIdx.x * blockDim.x + threadIdx.x;   // over 64*4096
    int e = idx >> 12;
    int k = idx & 4095;
    g_wt[k * NEXP + e] = W[idx];
}

__device__ __forceinline__ unsigned smem_u32(const void* p) {
    return (unsigned)__cvta_generic_to_shared(p);
}

__global__ __launch_bounds__(NTHREADS)
void router_kernel(const float* __restrict__ x,
                   float* __restrict__ out,
                   int out_size)
{
    extern __shared__ float sm[];
    const unsigned sbase = smem_u32(sm);

    const int tid   = threadIdx.x;
    const int tok0  = blockIdx.x * BT;
    const int ehalf = tid >> 6;        // expert half: experts ehalf*32 .. +31
    const int trow  = tid & 63;        // tokens trow, trow+64

    // acc[t][q] : f32x2 over expert pair (ehalf*32 + 2q, +2q+1), t in {trow, trow+64}
    unsigned long long acc[2][16];
#pragma unroll
    for (int t = 0; t < 2; t++)
#pragma unroll
        for (int q = 0; q < 16; q++) acc[t][q] = 0ull;

    // x loader: thread owns token row `tid`, 32 floats per chunk (8 float4)
    const float* xsrc = x + (size_t)(tok0 + tid) * DIM;
    float4 xv[8];

    // ---- prologue: x chunk 0 -> regs, W chunk 0 -> smem stage 0 ----
#pragma unroll
    for (int f = 0; f < 8; f++)
        xv[f] = *(const float4*)(xsrc + f * 4);
    {
        const float* wsrc = g_wt;
        const unsigned wdst = sbase + XS_FLOATS * 4;
#pragma unroll
        for (int i = 0; i < 4; i++) {
            int m = i * NTHREADS + tid;            // 0..511 (16B units)
            asm volatile("cp.async.cg.shared.global [%0], [%1], 16;\n"
                         :: "r"(wdst + m * 16), "l"(wsrc + m * 4));
        }
        asm volatile("cp.async.commit_group;\n");
    }

    for (int c = 0; c < NC; c++) {
        const unsigned xs_b = sbase + (unsigned)(c & 1) * STAGE_BYTES;
        const unsigned ws_b = xs_b + XS_FLOATS * 4;

        __syncthreads();   // stage (c&1): readers from chunk c-2 are done

        // store x chunk c (row-major, stride 33): conflict-free STS.32
        {
            float* xrow = sm + (c & 1) * STAGE_FLOATS + tid * SXROW;
#pragma unroll
            for (int f = 0; f < 8; f++) {
                xrow[f * 4 + 0] = xv[f].x;
                xrow[f * 4 + 1] = xv[f].y;
                xrow[f * 4 + 2] = xv[f].z;
                xrow[f * 4 + 3] = xv[f].w;
            }
        }

        if (c + 1 < NC) {
            const float* xs2 = xsrc + (c + 1) * KC;
#pragma unroll
            for (int f = 0; f < 8; f++)
                xv[f] = *(const float4*)(xs2 + f * 4);

            const float* wsrc = g_wt + (size_t)(c + 1) * WS_FLOATS;
            const unsigned wdst = sbase + (unsigned)((c + 1) & 1) * STAGE_BYTES
                                  + XS_FLOATS * 4;
#pragma unroll
            for (int i = 0; i < 4; i++) {
                int m = i * NTHREADS + tid;
                asm volatile("cp.async.cg.shared.global [%0], [%1], 16;\n"
                             :: "r"(wdst + m * 16), "l"(wsrc + m * 4));
            }
            asm volatile("cp.async.commit_group;\n");
            asm volatile("cp.async.wait_group 1;\n");
        } else {
            asm volatile("cp.async.wait_group 0;\n");
        }

        __syncthreads();

        // ---- compute chunk c ----
        // per kk: 2 LDS.32 (x, conflict-free) + 2 splats + 8 LDS.128 (w, warp-broadcast) + 32 FFMA2
        const unsigned xa = xs_b + (unsigned)(trow * SXROW * 4);
        const unsigned wa = ws_b + (unsigned)(ehalf * 128);
#pragma unroll 8
        for (int kk = 0; kk < KC; kk++) {
            float xv0, xv1;
            asm("ld.shared.f32 %0, [%1];" : "=f"(xv0) : "r"(xa + kk * 4));
            asm("ld.shared.f32 %0, [%1];" : "=f"(xv1) : "r"(xa + kk * 4 + 64 * SXROW * 4));
            unsigned long long xs0, xs1;
            asm("mov.b64 %0, {%1, %1};" : "=l"(xs0) : "f"(xv0));
            asm("mov.b64 %0, {%1, %1};" : "=l"(xs1) : "f"(xv1));

            const unsigned wk = wa + (unsigned)(kk * 256);
#pragma unroll
            for (int h = 0; h < 4; h++) {   // 8 LDS.128 total, all lanes same addr (broadcast)
                unsigned long long w0, w1, w2, w3;
                asm("ld.shared.v2.u64 {%0,%1}, [%2];"
                    : "=l"(w0), "=l"(w1) : "r"(wk + h * 32));
                asm("ld.shared.v2.u64 {%0,%1}, [%2];"
                    : "=l"(w2), "=l"(w3) : "r"(wk + h * 32 + 16));
                asm("fma.rn.f32x2 %0, %1, %2, %0;" : "+l"(acc[0][4*h+0]) : "l"(xs0), "l"(w0));
                asm("fma.rn.f32x2 %0, %1, %2, %0;" : "+l"(acc[0][4*h+1]) : "l"(xs0), "l"(w1));
                asm("fma.rn.f32x2 %0, %1, %2, %0;" : "+l"(acc[0][4*h+2]) : "l"(xs0), "l"(w2));
                asm("fma.rn.f32x2 %0, %1, %2, %0;" : "+l"(acc[0][4*h+3]) : "l"(xs0), "l"(w3));
                asm("fma.rn.f32x2 %0, %1, %2, %0;" : "+l"(acc[1][4*h+0]) : "l"(xs1), "l"(w0));
                asm("fma.rn.f32x2 %0, %1, %2, %0;" : "+l"(acc[1][4*h+1]) : "l"(xs1), "l"(w1));
                asm("fma.rn.f32x2 %0, %1, %2, %0;" : "+l"(acc[1][4*h+2]) : "l"(xs1), "l"(w2));
                asm("fma.rn.f32x2 %0, %1, %2, %0;" : "+l"(acc[1][4*h+3]) : "l"(xs1), "l"(w3));
            }
        }
    }

    // ---- dump logits: lg[128][SROWL] ----
    __syncthreads();
    float* lg = sm;
#pragma unroll
    for (int t = 0; t < 2; t++) {
        int tok = trow + t * 64;
#pragma unroll
        for (int q = 0; q < 16; q++) {
            float lo, hi;
            asm("mov.b64 {%0, %1}, %2;" : "=f"(lo), "=f"(hi) : "l"(acc[t][q]));
            int e = ehalf * 32 + 2 * q;
            lg[tok * SROWL + e]     = lo;
            lg[tok * SROWL + e + 1] = hi;
        }
    }
    __syncthreads();

    // ---- fused top-8 + softmax: one thread per token ----
    {
        const int t = tid;
        float* row = lg + t * SROWL;

        float cv[TOPK];
        int   ci[TOPK];
#pragma unroll
        for (int r = 0; r < TOPK; r++) {
            float best = NEG_INF;
            int   bi   = 0;
            for (int e = 0; e < NEXP; e++) {
                float v = row[e];
                if (v > best) { best = v; bi = e; }  // strict >: ties -> lowest index
            }
            row[bi] = NEG_INF;
            cv[r] = best;
            ci[r] = bi;
        }

        float m = cv[0];
        float ex[TOPK], s = 0.f;
#pragma unroll
        for (int r = 0; r < TOPK; r++) { ex[r] = __expf(cv[r] - m); s += ex[r]; }
        float inv = 1.f / s;

        int gt = tok0 + t;
#pragma unroll
        for (int r = 0; r < TOPK; r++)
            out[gt * TOPK + r] = ex[r] * inv;

        if (out_size >= 2 * TOKENS * TOPK) {
#pragma unroll
            for (int r = 0; r < TOPK; r++)
                out[TOKENS * TOPK + gt * TOPK + r] = (float)ci[r];
        }
    }
}

extern "C" void kernel_launch(void* const* d_in, const int* in_sizes, int n_in,
                              void* d_out, int out_size)
{
    const float* x = (const float*)d_in[0];   // [16384, 4096]
    const float* W = (const float*)d_in[1];   // [64, 4096]
    float* out = (float*)d_out;

    cudaFuncSetAttribute(router_kernel,
                         cudaFuncAttributeMaxDynamicSharedMemorySize, SMEM_BYTES);

    wt_kernel<<<(NEXP * DIM) / 256, 256>>>(W);
    router_kernel<<<TOKENS / BT, NTHREADS, SMEM_BYTES>>>(x, out, out_size);
}

// round 7
// speedup vs baseline: 1.5702x; 1.3272x over previous
#include <cuda_runtime.h>
#include <cstdint>

#define TOKENS   16384
#define DIM      4096
#define NEXP     64
#define TOPK     8
#define BT       128           // tokens per block
#define KC       32            // k-chunk
#define NC       (DIM / KC)    // 128 chunks
#define NTHREADS 256

#define SXROW    33                          // x row stride in floats (odd -> conflict-free col reads)
#define XS_FLOATS (BT * SXROW)               // 4224
#define WS_FLOATS (KC * NEXP)                // 2048
#define STAGE_FLOATS (XS_FLOATS + WS_FLOATS) // 6272
#define STAGE_BYTES  (STAGE_FLOATS * 4)      // 25088
#define SMEM_BYTES   (2 * STAGE_BYTES)       // 50176

#define SROWL    66
#define NEG_INF (-3.0e38f)

// W transposed: g_wt[k*64 + e] = W[e][k]
__device__ float g_wt[DIM * NEXP];

__global__ void wt_kernel(const float* __restrict__ W)
{
    int idx = blockIdx.x * blockDim.x + threadIdx.x;   // over 64*4096
    int e = idx >> 12;
    int k = idx & 4095;
    g_wt[k * NEXP + e] = W[idx];
}

__device__ __forceinline__ unsigned smem_u32(const void* p) {
    return (unsigned)__cvta_generic_to_shared(p);
}

__global__ __launch_bounds__(NTHREADS)
void router_kernel(const float* __restrict__ x,
                   float* __restrict__ out,
                   int out_size)
{
    extern __shared__ float sm[];
    const unsigned sbase = smem_u32(sm);

    const int tid  = threadIdx.x;
    const int tok0 = blockIdx.x * BT;
    const int eq   = tid >> 6;        // expert quarter: experts eq*16 .. +15 (uniform per warp)
    const int trow = tid & 63;        // tokens trow, trow+64

    // acc[t][p] : f32x2 over expert pair (eq*16 + 2p, +2p+1), t in {trow, trow+64}
    unsigned long long acc[2][8];
#pragma unroll
    for (int t = 0; t < 2; t++)
#pragma unroll
        for (int p = 0; p < 8; p++) acc[t][p] = 0ull;

    // x loader: 2 threads per token row, 64B each (4 float4)
    const int lrow  = tid >> 1;
    const int lhalf = tid & 1;
    const float* xsrc = x + (size_t)(tok0 + lrow) * DIM + lhalf * 16;
    float4 xv[4];

    // ---- prologue: x chunk 0 -> regs, W chunk 0 -> smem stage 0 ----
#pragma unroll
    for (int f = 0; f < 4; f++)
        xv[f] = *(const float4*)(xsrc + f * 4);
    {
        const float* wsrc = g_wt;
        const unsigned wdst = sbase + XS_FLOATS * 4;
#pragma unroll
        for (int i = 0; i < 2; i++) {
            int m = i * NTHREADS + tid;            // 0..511 (16B units)
            asm volatile("cp.async.cg.shared.global [%0], [%1], 16;\n"
                         :: "r"(wdst + m * 16), "l"(wsrc + m * 4));
        }
        asm volatile("cp.async.commit_group;\n");
    }

    for (int c = 0; c < NC; c++) {
        const unsigned xs_b = sbase + (unsigned)(c & 1) * STAGE_BYTES;
        const unsigned ws_b = xs_b + XS_FLOATS * 4;

        __syncthreads();   // stage (c&1): readers from chunk c-2 are done

        // store x chunk c (row-major, stride 33): conflict-free STS.32
        {
            float* xrow = sm + (c & 1) * STAGE_FLOATS + lrow * SXROW + lhalf * 16;
#pragma unroll
            for (int f = 0; f < 4; f++) {
                xrow[f * 4 + 0] = xv[f].x;
                xrow[f * 4 + 1] = xv[f].y;
                xrow[f * 4 + 2] = xv[f].z;
                xrow[f * 4 + 3] = xv[f].w;
            }
        }

        if (c + 1 < NC) {
            const float* xs2 = xsrc + (c + 1) * KC;
#pragma unroll
            for (int f = 0; f < 4; f++)
                xv[f] = *(const float4*)(xs2 + f * 4);

            const float* wsrc = g_wt + (size_t)(c + 1) * WS_FLOATS;
            const unsigned wdst = sbase + (unsigned)((c + 1) & 1) * STAGE_BYTES
                                  + XS_FLOATS * 4;
#pragma unroll
            for (int i = 0; i < 2; i++) {
                int m = i * NTHREADS + tid;
                asm volatile("cp.async.cg.shared.global [%0], [%1], 16;\n"
                             :: "r"(wdst + m * 16), "l"(wsrc + m * 4));
            }
            asm volatile("cp.async.commit_group;\n");
            asm volatile("cp.async.wait_group 1;\n");
        } else {
            asm volatile("cp.async.wait_group 0;\n");
        }

        __syncthreads();

        // ---- compute chunk c ----
        // per kk per thread: 2 LDS.32 (x) + 2 splats + 4 LDS.128 (W, warp-broadcast) + 16 FFMA2
        const unsigned xa = xs_b + (unsigned)(trow * SXROW * 4);
        const unsigned wa = ws_b + (unsigned)(eq * 64);     // eq*16 floats
#pragma unroll 8
        for (int kk = 0; kk < KC; kk++) {
            float xv0, xv1;
            asm("ld.shared.f32 %0, [%1];" : "=f"(xv0) : "r"(xa + kk * 4));
            asm("ld.shared.f32 %0, [%1];" : "=f"(xv1) : "r"(xa + kk * 4 + 64 * SXROW * 4));
            unsigned long long xs0, xs1;
            asm("mov.b64 %0, {%1, %1};" : "=l"(xs0) : "f"(xv0));
            asm("mov.b64 %0, {%1, %1};" : "=l"(xs1) : "f"(xv1));

            const unsigned wk = wa + (unsigned)(kk * 256);
#pragma unroll
            for (int h = 0; h < 4; h++) {   // 4 broadcast LDS.128 -> 8 expert pairs
                unsigned long long w0, w1;
                asm("ld.shared.v2.u64 {%0,%1}, [%2];"
                    : "=l"(w0), "=l"(w1) : "r"(wk + h * 16));
                asm("fma.rn.f32x2 %0, %1, %2, %0;" : "+l"(acc[0][2*h+0]) : "l"(xs0), "l"(w0));
                asm("fma.rn.f32x2 %0, %1, %2, %0;" : "+l"(acc[0][2*h+1]) : "l"(xs0), "l"(w1));
                asm("fma.rn.f32x2 %0, %1, %2, %0;" : "+l"(acc[1][2*h+0]) : "l"(xs1), "l"(w0));
                asm("fma.rn.f32x2 %0, %1, %2, %0;" : "+l"(acc[1][2*h+1]) : "l"(xs1), "l"(w1));
            }
        }
    }

    // ---- dump logits: lg[128][SROWL] ----
    __syncthreads();
    float* lg = sm;
#pragma unroll
    for (int t = 0; t < 2; t++) {
        int tok = trow + t * 64;
#pragma unroll
        for (int p = 0; p < 8; p++) {
            float lo, hi;
            asm("mov.b64 {%0, %1}, %2;" : "=f"(lo), "=f"(hi) : "l"(acc[t][p]));
            int e = eq * 16 + 2 * p;
            lg[tok * SROWL + e]     = lo;
            lg[tok * SROWL + e + 1] = hi;
        }
    }
    __syncthreads();

    // ---- fused top-8 + softmax: one thread per token ----
    if (tid < BT) {
        const int t = tid;
        float* row = lg + t * SROWL;

        float cv[TOPK];
        int   ci[TOPK];
#pragma unroll
        for (int r = 0; r < TOPK; r++) {
            float best = NEG_INF;
            int   bi   = 0;
            for (int e = 0; e < NEXP; e++) {
                float v = row[e];
                if (v > best) { best = v; bi = e; }  // strict >: ties -> lowest index
            }
            row[bi] = NEG_INF;
            cv[r] = best;
            ci[r] = bi;
        }

        float m = cv[0];
        float ex[TOPK], s = 0.f;
#pragma unroll
        for (int r = 0; r < TOPK; r++) { ex[r] = __expf(cv[r] - m); s += ex[r]; }
        float inv = 1.f / s;

        int gt = tok0 + t;
#pragma unroll
        for (int r = 0; r < TOPK; r++)
            out[gt * TOPK + r] = ex[r] * inv;

        if (out_size >= 2 * TOKENS * TOPK) {
#pragma unroll
            for (int r = 0; r < TOPK; r++)
                out[TOKENS * TOPK + gt * TOPK + r] = (float)ci[r];
        }
    }
}

extern "C" void kernel_launch(void* const* d_in, const int* in_sizes, int n_in,
                              void* d_out, int out_size)
{
    const float* x = (const float*)d_in[0];   // [16384, 4096]
    const float* W = (const float*)d_in[1];   // [64, 4096]
    float* out = (float*)d_out;

    cudaFuncSetAttribute(router_kernel,
                         cudaFuncAttributeMaxDynamicSharedMemorySize, SMEM_BYTES);

    wt_kernel<<<(NEXP * DIM) / 256, 256>>>(W);
    router_kernel<<<TOKENS / BT, NTHREADS, SMEM_BYTES>>>(x, out, out_size);
}

// round 9
// speedup vs baseline: 1.7211x; 1.0961x over previous
#include <cuda_runtime.h>
#include <cstdint>

#define TOKENS   16384
#define DIM      4096
#define NEXP     64
#define TOPK     8
#define BT       64            // tokens per block
#define KC       32            // k-chunk
#define NC       (DIM / KC)    // 128 chunks
#define NTHREADS 256

#define SXROW    65                          // xs row stride (odd -> conflict-free STS + LDS)
#define XS_FLOATS (KC * SXROW)               // 2080
#define WS_FLOATS (KC * NEXP)                // 2048
#define STAGE_FLOATS (XS_FLOATS + WS_FLOATS) // 4128
#define STAGE_BYTES  (STAGE_FLOATS * 4)      // 16512
#define SMEM_BYTES   (2 * STAGE_BYTES)       // 33024  -> 2 CTAs/SM fits easily

#define SROWL    66
#define NEG_INF (-3.0e38f)

// W transposed: g_wt[k*64 + e] = W[e][k]
__device__ float g_wt[DIM * NEXP];

__global__ void wt_kernel(const float* __restrict__ W)
{
    int idx = blockIdx.x * blockDim.x + threadIdx.x;   // over 64*4096
    int e = idx >> 12;
    int k = idx & 4095;
    g_wt[k * NEXP + e] = W[idx];
}

__device__ __forceinline__ unsigned smem_u32(const void* p) {
    return (unsigned)__cvta_generic_to_shared(p);
}

__global__ __launch_bounds__(NTHREADS, 2)
void router_kernel(const float* __restrict__ x,
                   float* __restrict__ out,
                   int out_size)
{
    extern __shared__ float sm[];
    const unsigned sbase = smem_u32(sm);

    const int tid  = threadIdx.x;
    const int tok0 = blockIdx.x * BT;
    const int eo   = tid >> 5;        // warp id == expert octet: experts eo*8..+7 (warp-uniform)
    const int trow = tid & 31;        // tokens trow, trow+32

    // acc[t][p] : f32x2 over expert pair (eo*8 + 2p, 2p+1), t in {trow, trow+32}
    unsigned long long acc[2][4];
#pragma unroll
    for (int t = 0; t < 2; t++)
#pragma unroll
        for (int p = 0; p < 4; p++) acc[t][p] = 0ull;

    // x loader: 4 threads per token row, 8 floats each (2 float4)
    const int lrow = tid >> 2;        // token row 0..63
    const int lq   = tid & 3;         // 8-float quad within chunk
    const float* xsrc = x + (size_t)(tok0 + lrow) * DIM + lq * 8;
    float4 xv[2];

    // ---- prologue: x chunk 0 -> regs, W chunk 0 -> smem stage 0 ----
    xv[0] = *(const float4*)(xsrc);
    xv[1] = *(const float4*)(xsrc + 4);
    {
        const float* wsrc = g_wt;
        const unsigned wdst = sbase + XS_FLOATS * 4;
#pragma unroll
        for (int i = 0; i < 2; i++) {
            int m = i * NTHREADS + tid;            // 0..511 (16B units)
            asm volatile("cp.async.cg.shared.global [%0], [%1], 16;\n"
                         :: "r"(wdst + m * 16), "l"(wsrc + m * 4));
        }
        asm volatile("cp.async.commit_group;\n");
    }

    for (int c = 0; c < NC; c++) {
        const unsigned xs_b = sbase + (unsigned)(c & 1) * STAGE_BYTES;
        const unsigned ws_b = xs_b + XS_FLOATS * 4;

        __syncthreads();   // stage (c&1): readers from chunk c-2 are done

        // store x chunk c transposed: xs[kk][token], stride 65 (conflict-free)
        {
            float* base = sm + (c & 1) * STAGE_FLOATS + lrow;
            const float v[8] = { xv[0].x, xv[0].y, xv[0].z, xv[0].w,
                                 xv[1].x, xv[1].y, xv[1].z, xv[1].w };
#pragma unroll
            for (int j = 0; j < 8; j++)
                base[(lq * 8 + j) * SXROW] = v[j];
        }

        if (c + 1 < NC) {
            const float* xs2 = xsrc + (c + 1) * KC;
            xv[0] = *(const float4*)(xs2);
            xv[1] = *(const float4*)(xs2 + 4);

            const float* wsrc = g_wt + (size_t)(c + 1) * WS_FLOATS;
            const unsigned wdst = sbase + (unsigned)((c + 1) & 1) * STAGE_BYTES
                                  + XS_FLOATS * 4;
#pragma unroll
            for (int i = 0; i < 2; i++) {
                int m = i * NTHREADS + tid;
                asm volatile("cp.async.cg.shared.global [%0], [%1], 16;\n"
                             :: "r"(wdst + m * 16), "l"(wsrc + m * 4));
            }
            asm volatile("cp.async.commit_group;\n");
            asm volatile("cp.async.wait_group 1;\n");
        } else {
            asm volatile("cp.async.wait_group 0;\n");
        }

        __syncthreads();

        // ---- compute chunk c: manual kk software pipeline ----
        // per kk per thread: 2 LDS.32 (x) + 2 splats + 2 LDS.128 (W broadcast) + 8 FFMA2
        const unsigned xa = xs_b + (unsigned)(trow * 4);
        const unsigned wa = ws_b + (unsigned)(eo * 32);

        unsigned long long xsp[2][2];   // [buf][token] splat {x,x}
        unsigned long long wреg_dummy;  (void)wреg_dummy;
        unsigned long long wr[2][4];    // [buf][u64 half of LDS.128 pair]

#define LOADKK(B, KKV)                                                          \
        {                                                                       \
            float xv0_, xv1_;                                                   \
            asm("ld.shared.f32 %0, [%1];" : "=f"(xv0_) : "r"(xa + (KKV) * (SXROW*4)));          \
            asm("ld.shared.f32 %0, [%1];" : "=f"(xv1_) : "r"(xa + (KKV) * (SXROW*4) + 128));    \
            asm("mov.b64 %0, {%1, %1};" : "=l"(xsp[B][0]) : "f"(xv0_));         \
            asm("mov.b64 %0, {%1, %1};" : "=l"(xsp[B][1]) : "f"(xv1_));         \
            asm("ld.shared.v2.u64 {%0,%1}, [%2];"                               \
                : "=l"(wr[B][0]), "=l"(wr[B][1]) : "r"(wa + (KKV) * 256));      \
            asm("ld.shared.v2.u64 {%0,%1}, [%2];"                               \
                : "=l"(wr[B][2]), "=l"(wr[B][3]) : "r"(wa + (KKV) * 256 + 16)); \
        }
#define FMAKK(B)                                                                \
        {                                                                       \
            asm("fma.rn.f32x2 %0, %1, %2, %0;" : "+l"(acc[0][0]) : "l"(xsp[B][0]), "l"(wr[B][0])); \
            asm("fma.rn.f32x2 %0, %1, %2, %0;" : "+l"(acc[0][1]) : "l"(xsp[B][0]), "l"(wr[B][1])); \
            asm("fma.rn.f32x2 %0, %1, %2, %0;" : "+l"(acc[0][2]) : "l"(xsp[B][0]), "l"(wr[B][2])); \
            asm("fma.rn.f32x2 %0, %1, %2, %0;" : "+l"(acc[0][3]) : "l"(xsp[B][0]), "l"(wr[B][3])); \
            asm("fma.rn.f32x2 %0, %1, %2, %0;" : "+l"(acc[1][0]) : "l"(xsp[B][1]), "l"(wr[B][0])); \
            asm("fma.rn.f32x2 %0, %1, %2, %0;" : "+l"(acc[1][1]) : "l"(xsp[B][1]), "l"(wr[B][1])); \
            asm("fma.rn.f32x2 %0, %1, %2, %0;" : "+l"(acc[1][2]) : "l"(xsp[B][1]), "l"(wr[B][2])); \
            asm("fma.rn.f32x2 %0, %1, %2, %0;" : "+l"(acc[1][3]) : "l"(xsp[B][1]), "l"(wr[B][3])); \
        }

        LOADKK(0, 0)
#pragma unroll
        for (int kk = 0; kk < KC - 1; kk++) {
            LOADKK((kk + 1) & 1, kk + 1)
            FMAKK(kk & 1)
        }
        FMAKK((KC - 1) & 1)
#undef LOADKK
#undef FMAKK
    }

    // ---- dump logits: lg[64][SROWL] ----
    __syncthreads();
    float* lg = sm;
#pragma unroll
    for (int t = 0; t < 2; t++) {
        int tok = trow + t * 32;
#pragma unroll
        for (int p = 0; p < 4; p++) {
            float lo, hi;
            asm("mov.b64 {%0, %1}, %2;" : "=f"(lo), "=f"(hi) : "l"(acc[t][p]));
            int e = eo * 8 + 2 * p;
            lg[tok * SROWL + e]     = lo;
            lg[tok * SROWL + e + 1] = hi;
        }
    }
    __syncthreads();

    // ---- fused top-8 + softmax: one thread per token ----
    if (tid < BT) {
        const int t = tid;
        float* row = lg + t * SROWL;

        float cv[TOPK];
        int   ci[TOPK];
#pragma unroll
        for (int r = 0; r < TOPK; r++) {
            float best = NEG_INF;
            int   bi   = 0;
            for (int e = 0; e < NEXP; e++) {
                float v = row[e];
                if (v > best) { best = v; bi = e; }  // strict >: ties -> lowest index
            }
            row[bi] = NEG_INF;
            cv[r] = best;
            ci[r] = bi;
        }

        float m = cv[0];
        float ex[TOPK], s = 0.f;
#pragma unroll
        for (int r = 0; r < TOPK; r++) { ex[r] = __expf(cv[r] - m); s += ex[r]; }
        float inv = 1.f / s;

        int gt = tok0 + t;
#pragma unroll
        for (int r = 0; r < TOPK; r++)
            out[gt * TOPK + r] = ex[r] * inv;

        if (out_size >= 2 * TOKENS * TOPK) {
#pragma unroll
            for (int r = 0; r < TOPK; r++)
                out[TOKENS * TOPK + gt * TOPK + r] = (float)ci[r];
        }
    }
}

extern "C" void kernel_launch(void* const* d_in, const int* in_sizes, int n_in,
                              void* d_out, int out_size)
{
    const float* x = (const float*)d_in[0];   // [16384, 4096]
    const float* W = (const float*)d_in[1];   // [64, 4096]
    float* out = (float*)d_out;

    cudaFuncSetAttribute(router_kernel,
                         cudaFuncAttributeMaxDynamicSharedMemorySize, SMEM_BYTES);

    wt_kernel<<<(NEXP * DIM) / 256, 256>>>(W);
    router_kernel<<<TOKENS / BT, NTHREADS, SMEM_BYTES>>>(x, out, out_size);
}